// round 14
// baseline (speedup 1.0000x reference)
#include <cuda_runtime.h>
#include <cuda_fp16.h>
#include <math.h>
#include <stdint.h>

#define NN 4096
#define D_IN 512
#define HID 256
#define CC 64
#define K_ITER 10
#define KC 4      // split chunks
#define NBLK 128  // persistent grid size (co-resident: 1 CTA/SM, 128 < 148 SMs)

#define SCAD_A_ 3.7f
#define LAM_BASE_ 0.11111111111111116f
#define EPS_ 1e-6f
#define DIST_EPS_ 1e-8f

// ---------------- static device scratch ----------------
__device__ __align__(16) __half g_Af16[(size_t)NN * NN];
__device__ __align__(16) __half g_FtHi[CC * NN];
__device__ __align__(16) __half g_Xhi[NN * D_IN];
__device__ __align__(16) __half g_Xlo[NN * D_IN];
__device__ __align__(16) __half g_W1Thi[HID * D_IN];
__device__ __align__(16) __half g_W1Tlo[HID * D_IN];
__device__ __align__(16) __half g_W2Thi[CC * HID];
__device__ __align__(16) __half g_W2Tlo[CC * HID];
__device__ __align__(16) __half g_H1hi[NN * HID];
__device__ __align__(16) __half g_H1lo[NN * HID];
__device__ __align__(16) float g_q0[NN];
__device__ __align__(16) float g_F0[NN * CC];
__device__ __align__(16) float g_Fa[NN * CC];
__device__ __align__(16) float g_Fb[NN * CC];
__device__ __align__(16) float g_YT[CC * NN];
__device__ __align__(16) float g_sq[NN];
__device__ __align__(16) float g_invd[NN];
__device__ __align__(16) float g_rawlam[NN];
__device__ __align__(16) float g_lam[NN];
__device__ __align__(16) float g_accp[(size_t)KC * NN * CC];
__device__ __align__(16) float g_qp[KC * NN];
__device__ int g_maxbits[K_ITER];  // atomicMax of float bits; replay-idempotent
__device__ unsigned g_cnt;         // barrier arrivals (returns to 0 each barrier)
__device__ unsigned g_gen;         // barrier generation (monotone; replay-safe)

// ---------------- L1-bypassing loads (persistent-kernel coherence) ----------------
__device__ __forceinline__ float4 ldcg4(const float* p) {
    float4 v;
    asm volatile("ld.global.cg.v4.f32 {%0,%1,%2,%3}, [%4];"
                 : "=f"(v.x), "=f"(v.y), "=f"(v.z), "=f"(v.w) : "l"(p));
    return v;
}
__device__ __forceinline__ float ldcgf(const float* p) {
    float v;
    asm volatile("ld.global.cg.f32 %0, [%1];" : "=f"(v) : "l"(p));
    return v;
}
__device__ __forceinline__ int ldcgi(const int* p) {
    int v;
    asm volatile("ld.global.cg.s32 %0, [%1];" : "=r"(v) : "l"(p));
    return v;
}

__device__ __forceinline__ bool fast_ok_cg(const float* __restrict__ log_lams, int k) {
    float lam = expf(log_lams[k]);
    float maxsq = __int_as_float(ldcgi(&g_maxbits[k]));
    return 4.0f * maxsq + DIST_EPS_ <= 0.25f * lam * lam;
}
__device__ __forceinline__ bool fast_ok(const float* __restrict__ log_lams, int k) {
    float lam = expf(log_lams[k]);
    float maxsq = __int_as_float(g_maxbits[k]);
    return 4.0f * maxsq + DIST_EPS_ <= 0.25f * lam * lam;
}

__device__ __forceinline__ uint32_t s2u(const void* p) {
    uint32_t a;
    asm("{ .reg .u64 t; cvta.to.shared.u64 t, %1; cvt.u32.u64 %0, t; }" : "=r"(a) : "l"(p));
    return a;
}
#define CP16(dst, src) asm volatile("cp.async.cg.shared.global [%0], [%1], 16;" :: "r"(dst), "l"(src))
#define CPCOMMIT() asm volatile("cp.async.commit_group;" ::: "memory")
#define CPWAIT(n) asm volatile("cp.async.wait_group %0;" :: "n"(n) : "memory")
#define LDSM4(r, addr)                                                             \
    asm volatile("ldmatrix.sync.aligned.m8n8.x4.shared.b16 {%0,%1,%2,%3}, [%4];"   \
                 : "=r"((r)[0]), "=r"((r)[1]), "=r"((r)[2]), "=r"((r)[3])          \
                 : "r"(addr))
#define MMAF16(c, a, b0, b1)                                                       \
    asm volatile("mma.sync.aligned.m16n8k16.row.col.f32.f16.f16.f32 "              \
                 "{%0,%1,%2,%3},{%4,%5,%6,%7},{%8,%9},{%0,%1,%2,%3};"              \
                 : "+f"((c)[0]), "+f"((c)[1]), "+f"((c)[2]), "+f"((c)[3])          \
                 : "r"((a)[0]), "r"((a)[1]), "r"((a)[2]), "r"((a)[3]),             \
                   "r"(b0), "r"(b1))

// ---------------- grid barrier (all NBLK blocks co-resident) ----------------
__device__ __forceinline__ void gridbar() {
    __syncthreads();
    __threadfence();
    if (threadIdx.x == 0) {
        unsigned gen = *(volatile unsigned*)&g_gen;
        if (atomicAdd(&g_cnt, 1u) == NBLK - 1) {
            g_cnt = 0;
            __threadfence();
            atomicAdd(&g_gen, 1u);
        } else {
            while (*(volatile unsigned*)&g_gen == gen) {}
        }
    }
    __syncthreads();
}

// ---------------- setup: degree ----------------
__global__ void deg_kernel(const float* __restrict__ A) {
    __shared__ float sm[256];
    int row = blockIdx.x;
    const float4* ap = (const float4*)(A + (size_t)row * NN);
    float s = 0.0f;
    for (int j = threadIdx.x; j < NN / 4; j += 256) {
        float4 v = ap[j];
        s += (v.x + v.y) + (v.z + v.w);
    }
    sm[threadIdx.x] = s;
    __syncthreads();
    for (int off = 128; off; off >>= 1) {
        if (threadIdx.x < off) sm[threadIdx.x] += sm[threadIdx.x + off];
        __syncthreads();
    }
    if (threadIdx.x == 0) g_invd[row] = 1.0f / sqrtf(sm[0] + 1.0f);
}

// ---------------- setup: A_tilde -> fp16 + q0 ----------------
__global__ void asplit_kernel(const float* __restrict__ A) {
    __shared__ float sm[256];
    const int i = blockIdx.x;
    const float di = g_invd[i];
    float qs = 0.0f;
    for (int j4 = threadIdx.x; j4 < NN / 4; j4 += 256) {
        const int j = j4 * 4;
        float4 a = *(const float4*)&A[(size_t)i * NN + j];
        float at[4];
        at[0] = (a.x + ((i == j + 0) ? 1.0f : 0.0f)) * di * g_invd[j + 0];
        at[1] = (a.y + ((i == j + 1) ? 1.0f : 0.0f)) * di * g_invd[j + 1];
        at[2] = (a.z + ((i == j + 2) ? 1.0f : 0.0f)) * di * g_invd[j + 2];
        at[3] = (a.w + ((i == j + 3) ? 1.0f : 0.0f)) * di * g_invd[j + 3];
        __align__(8) __half h[4];
#pragma unroll
        for (int t = 0; t < 4; t++) {
            qs += at[t];
            h[t] = __float2half_rn(at[t]);
        }
        *(uint2*)&g_Af16[(size_t)i * NN + j] = *(uint2*)&h[0];
    }
    sm[threadIdx.x] = qs;
    __syncthreads();
    for (int off = 128; off; off >>= 1) {
        if (threadIdx.x < off) sm[threadIdx.x] += sm[threadIdx.x + off];
        __syncthreads();
    }
    if (threadIdx.x == 0) g_q0[i] = sm[0];
}

// ---------------- setup: fused X split + W1/W2 transpose-split ----------------
#define PW_XB (NN * D_IN / 1024)
#define PW_W1B ((D_IN / 32) * (HID / 32))
#define PW_W2B ((HID / 32) * (CC / 32))
__global__ void prepw_kernel(const float* __restrict__ X, const float* __restrict__ W1,
                             const float* __restrict__ W2) {
    __shared__ float t[32][33];
    const int b = blockIdx.x;
    const int tid = threadIdx.x;
    if (b < PW_XB) {
        int idx = b * 256 + tid;
        float4 v = *(const float4*)&X[(size_t)idx * 4];
        __align__(8) __half h[4], l[4];
        float a[4] = {v.x, v.y, v.z, v.w};
#pragma unroll
        for (int q = 0; q < 4; q++) {
            h[q] = __float2half_rn(a[q]);
            l[q] = __float2half_rn(a[q] - __half2float(h[q]));
        }
        *(uint2*)&g_Xhi[(size_t)idx * 4] = *(uint2*)&h[0];
        *(uint2*)&g_Xlo[(size_t)idx * 4] = *(uint2*)&l[0];
        return;
    }
    const float* S;
    __half *Dhi, *Dlo;
    int rows, cols, bi, bj;
    if (b < PW_XB + PW_W1B) {
        int bb = b - PW_XB;
        rows = D_IN; cols = HID;
        bi = (bb >> 3) * 32; bj = (bb & 7) * 32;
        S = W1; Dhi = g_W1Thi; Dlo = g_W1Tlo;
    } else {
        int bb = b - PW_XB - PW_W1B;
        rows = HID; cols = CC;
        bi = (bb >> 1) * 32; bj = (bb & 1) * 32;
        S = W2; Dhi = g_W2Thi; Dlo = g_W2Tlo;
    }
    const int tx = tid & 31, ty = tid >> 5;
#pragma unroll
    for (int r = 0; r < 4; r++)
        t[ty + r * 8][tx] = S[(size_t)(bi + ty + r * 8) * cols + bj + tx];
    __syncthreads();
#pragma unroll
    for (int r = 0; r < 4; r++) {
        float v = t[tx][ty + r * 8];
        __half h = __float2half_rn(v);
        __half l = __float2half_rn(v - __half2float(h));
        Dhi[(size_t)(bj + ty + r * 8) * rows + bi + tx] = h;
        Dlo[(size_t)(bj + ty + r * 8) * rows + bi + tx] = l;
    }
}

// ---------------- prep helper: from smem F-rows (stride 65) emit FtHi/YT/sq/max ----------------
__device__ __forceinline__ void prep_from_smem(const float* s, const float* invd_s,
                                               float* sq_s, int j0, int knext, int tid) {
    if (tid < 64) {
        float acc = 0.0f;
#pragma unroll 8
        for (int c = 0; c < 64; c++) { float x = s[tid * 65 + c]; acc = fmaf(x, x, acc); }
        float iv = invd_s[tid];
        float sqv = acc * iv * iv;
        g_sq[j0 + tid] = sqv;
        sq_s[tid] = sqv;
    }
    {
        const int c = tid >> 2;
        const int js = (tid & 3) * 16;
        __align__(16) __half hb[16];
        __align__(16) float yv[16];
#pragma unroll
        for (int t = 0; t < 16; t++) {
            float x = s[(js + t) * 65 + c];
            hb[t] = __float2half_rn(x);
            yv[t] = x * invd_s[js + t];
        }
        size_t ob = (size_t)c * NN + j0 + js;
        *(uint4*)&g_FtHi[ob] = *(uint4*)&hb[0];
        *(uint4*)&g_FtHi[ob + 8] = *(uint4*)&hb[8];
#pragma unroll
        for (int q = 0; q < 4; q++) *(float4*)&g_YT[ob + q * 4] = *(float4*)&yv[q * 4];
    }
    __syncthreads();
    if (tid == 0) {
        float m = sq_s[0];
#pragma unroll 8
        for (int t = 1; t < 64; t++) m = fmaxf(m, sq_s[t]);
        atomicMax(&g_maxbits[knext], __float_as_int(m));
    }
}

// ---------------- MLP HMMA (fp16, 3-pass, M=128). OUTMODE: 1 = half hi/lo, 2 = F0 + prep + conf ----------------
#define AHI_OFF 0
#define ALO_OFF 10240
#define BHI_OFF 20480
#define BLO_OFF 25600
#define MLP_STAGE 30720
#define MLP_SMEM (2 * MLP_STAGE)
template <int RELU, int OUTMODE>
__global__ void __launch_bounds__(256) mlp_hmma(const __half* __restrict__ Ahi,
                                                const __half* __restrict__ Alo,
                                                const __half* __restrict__ Bhi,
                                                const __half* __restrict__ Blo,
                                                const float* __restrict__ bias,
                                                const float* __restrict__ raw_alpha,
                                                float* __restrict__ outF,
                                                __half* __restrict__ outHi,
                                                __half* __restrict__ outLo, int Kd, int Nd) {
    extern __shared__ char smem[];
    const uint32_t sb = s2u(smem);
    const int tid = threadIdx.x;
    const int wid = tid >> 5, lane = tid & 31;
    const int wm = (wid >> 1) * 32, wn = (wid & 1) * 32;
    const int i0 = blockIdx.y * 128, n0 = blockIdx.x * 64;

    float c[2][4][4];
#pragma unroll
    for (int a = 0; a < 2; a++)
#pragma unroll
        for (int b = 0; b < 4; b++)
#pragma unroll
            for (int d = 0; d < 4; d++) c[a][b][d] = 0.0f;

#define MLP_LOAD(T, BUF)                                                           \
    do {                                                                           \
        const int k0_ = (T) * 32;                                                  \
        const uint32_t bb_ = sb + (BUF) * MLP_STAGE;                               \
        _Pragma("unroll") for (int rep = 0; rep < 2; rep++) {                      \
            int q_ = tid + rep * 256;                                              \
            int row_ = q_ >> 2, cb_ = q_ & 3;                                      \
            CP16(bb_ + AHI_OFF + row_ * 80 + cb_ * 16,                             \
                 &Ahi[(size_t)(i0 + row_) * Kd + k0_ + cb_ * 8]);                  \
            CP16(bb_ + ALO_OFF + row_ * 80 + cb_ * 16,                             \
                 &Alo[(size_t)(i0 + row_) * Kd + k0_ + cb_ * 8]);                  \
        }                                                                          \
        {                                                                          \
            int row_ = tid >> 2, cb_ = tid & 3;                                    \
            CP16(bb_ + BHI_OFF + row_ * 80 + cb_ * 16,                             \
                 &Bhi[(size_t)(n0 + row_) * Kd + k0_ + cb_ * 8]);                  \
            CP16(bb_ + BLO_OFF + row_ * 80 + cb_ * 16,                             \
                 &Blo[(size_t)(n0 + row_) * Kd + k0_ + cb_ * 8]);                  \
        }                                                                          \
        CPCOMMIT();                                                                \
    } while (0)

    const int NT = Kd / 32;
    MLP_LOAD(0, 0);
    for (int t = 0; t < NT; t++) {
        if (t + 1 < NT) { MLP_LOAD(t + 1, (t + 1) & 1); CPWAIT(1); }
        else { CPWAIT(0); }
        __syncthreads();
        const uint32_t bb = sb + (t & 1) * MLP_STAGE;
#pragma unroll
        for (int ks = 0; ks < 2; ks++) {
            uint32_t ah[2][4], al[2][4], bh[2][4], bl[2][4];
#pragma unroll
            for (int mt = 0; mt < 2; mt++) {
                uint32_t addr = bb + AHI_OFF + (wm + mt * 16 + (lane & 15)) * 80 +
                                ks * 32 + (lane >> 4) * 16;
                LDSM4(ah[mt], addr);
                LDSM4(al[mt], addr + (ALO_OFF - AHI_OFF));
            }
#pragma unroll
            for (int p = 0; p < 2; p++) {
                uint32_t addr = bb + BHI_OFF +
                                (wn + p * 16 + (lane & 7) + ((lane >> 4) & 1) * 8) * 80 +
                                ks * 32 + ((lane >> 3) & 1) * 16;
                LDSM4(bh[p], addr);
                LDSM4(bl[p], addr + (BLO_OFF - BHI_OFF));
            }
#pragma unroll
            for (int mt = 0; mt < 2; mt++)
#pragma unroll
                for (int p = 0; p < 2; p++) {
                    MMAF16(c[mt][p * 2 + 0], ah[mt], bh[p][0], bh[p][1]);
                    MMAF16(c[mt][p * 2 + 1], ah[mt], bh[p][2], bh[p][3]);
                    MMAF16(c[mt][p * 2 + 0], ah[mt], bl[p][0], bl[p][1]);
                    MMAF16(c[mt][p * 2 + 1], ah[mt], bl[p][2], bl[p][3]);
                    MMAF16(c[mt][p * 2 + 0], al[mt], bh[p][0], bh[p][1]);
                    MMAF16(c[mt][p * 2 + 1], al[mt], bh[p][2], bh[p][3]);
                }
        }
        __syncthreads();
    }

    const int gr = lane >> 2, gc = (lane & 3) * 2;
    float* sbuf = (float*)smem;            // mode 2: 128 x 65
    float* invd_s = sbuf + 128 * 65;
    float* sq_s = invd_s + 128;
    if (OUTMODE == 2 && tid < 128) invd_s[tid] = g_invd[i0 + tid];
#pragma unroll
    for (int mt = 0; mt < 2; mt++)
#pragma unroll
        for (int nt = 0; nt < 4; nt++) {
            const int lcol = wn + (nt >> 1) * 16 + (nt & 1) * 8 + gc;
            const int col = n0 + lcol;
            const int lr0 = wm + mt * 16 + gr, lr1 = lr0 + 8;
            const int r0 = i0 + lr0, r1 = i0 + lr1;
            const float b0v = bias[col], b1v = bias[col + 1];
            float v00 = c[mt][nt][0] + b0v, v01 = c[mt][nt][1] + b1v;
            float v10 = c[mt][nt][2] + b0v, v11 = c[mt][nt][3] + b1v;
            if (RELU) {
                v00 = fmaxf(v00, 0.0f); v01 = fmaxf(v01, 0.0f);
                v10 = fmaxf(v10, 0.0f); v11 = fmaxf(v11, 0.0f);
            }
            if (OUTMODE == 1) {
                __half h00 = __float2half_rn(v00), h01 = __float2half_rn(v01);
                __half h10 = __float2half_rn(v10), h11 = __float2half_rn(v11);
                *(__half2*)&outHi[(size_t)r0 * Nd + col] = __halves2half2(h00, h01);
                *(__half2*)&outHi[(size_t)r1 * Nd + col] = __halves2half2(h10, h11);
                *(__half2*)&outLo[(size_t)r0 * Nd + col] = __halves2half2(
                    __float2half_rn(v00 - __half2float(h00)), __float2half_rn(v01 - __half2float(h01)));
                *(__half2*)&outLo[(size_t)r1 * Nd + col] = __halves2half2(
                    __float2half_rn(v10 - __half2float(h10)), __float2half_rn(v11 - __half2float(h11)));
            } else {
                *(float2*)&outF[(size_t)r0 * Nd + col] = make_float2(v00, v01);
                *(float2*)&outF[(size_t)r1 * Nd + col] = make_float2(v10, v11);
                if (OUTMODE == 2) {
                    sbuf[lr0 * 65 + lcol] = v00; sbuf[lr0 * 65 + lcol + 1] = v01;
                    sbuf[lr1 * 65 + lcol] = v10; sbuf[lr1 * 65 + lcol + 1] = v11;
                }
            }
        }
    if (OUTMODE == 2) {
        __syncthreads();
        {
            const float alpha = log1pf(expf(raw_alpha[0])) + 0.5f;
            const int wr0 = wid * 16;
            for (int rr = 0; rr < 16; rr++) {
                const int lr = wr0 + rr;
                float v0 = sbuf[lr * 65 + lane], v1 = sbuf[lr * 65 + lane + 32];
                float m = fmaxf(v0, v1);
#pragma unroll
                for (int off = 16; off; off >>= 1) m = fmaxf(m, __shfl_xor_sync(0xffffffffu, m, off));
                float e = expf(v0 - m) + expf(v1 - m);
#pragma unroll
                for (int off = 16; off; off >>= 1) e += __shfl_xor_sync(0xffffffffu, e, off);
                if (lane == 0) {
                    float conf = 1.0f / e;
                    conf = fminf(fmaxf(conf, EPS_), 1.0f - EPS_);
                    float base = fmaxf(1.0f - conf, EPS_);
                    g_rawlam[i0 + lr] = LAM_BASE_ * powf(base, alpha);
                }
            }
        }
        prep_from_smem(sbuf, invd_s, sq_s, i0, 0, tid);
        prep_from_smem(sbuf + 64 * 65, invd_s + 64, sq_s + 64, i0 + 64, 0, tid);
    }
}

// ---------------- PERSISTENT iteration kernel: meanlam + 10x(GEMM -> bar -> combine -> bar) ----------------
#define IA_OFF 0
#define IBH_OFF 18432
#define ITER_STAGE 27648
#define ITER_SMEM (3 * ITER_STAGE)
__global__ void __launch_bounds__(256) persist_kernel(const float* __restrict__ A,
                                                      float* __restrict__ out,
                                                      const float* __restrict__ log_lams) {
    extern __shared__ char smem[];
    const int tid = threadIdx.x;
    const int bid = blockIdx.x;
    const int kc = bid >> 5;   // 0..3
    const int by = bid & 31;   // 0..31

    // ---- phase 0: lambda normalization (block 0) ----
    if (bid == 0) {
        __shared__ float smr[256];
        float s = 0.0f;
        for (int i = tid; i < NN; i += 256) s += g_rawlam[i];
        smr[tid] = s;
        __syncthreads();
        for (int off = 128; off; off >>= 1) {
            if (tid < off) smr[tid] += smr[tid + off];
            __syncthreads();
        }
        float scale = LAM_BASE_ / fmaxf(smr[0] / (float)NN, EPS_);
        for (int i = tid; i < NN; i += 256) g_lam[i] = fmaxf(g_rawlam[i] * scale, EPS_);
    }
    gridbar();

    for (int k = 0; k < K_ITER; k++) {
        const float* F = (k == 0) ? g_F0 : ((k & 1) ? g_Fa : g_Fb);
        float* dst = (k == K_ITER - 1) ? out : ((k & 1) ? g_Fb : g_Fa);
        const bool fastk = fast_ok_cg(log_lams, k);

        if (fastk) {
            const uint32_t sb = s2u(smem);
            const int wid = tid >> 5, lane = tid & 31;
            const int wm = (wid >> 1) * 32, wn = (wid & 1) * 32;
            const int i0 = by * 128;
            const int kbase = kc * (NN / KC);

            float c[2][4][4];
#pragma unroll
            for (int a = 0; a < 2; a++)
#pragma unroll
                for (int b = 0; b < 4; b++)
#pragma unroll
                    for (int d = 0; d < 4; d++) c[a][b][d] = 0.0f;

#define ITER_LOAD(T, BUF)                                                          \
    do {                                                                           \
        const int k0_ = kbase + (T) * 64;                                          \
        const uint32_t bb_ = sb + (BUF) * ITER_STAGE;                              \
        _Pragma("unroll") for (int rep = 0; rep < 4; rep++) {                      \
            int q_ = tid + rep * 256;                                              \
            int row_ = q_ >> 3, cb_ = q_ & 7;                                      \
            CP16(bb_ + IA_OFF + row_ * 144 + cb_ * 16,                             \
                 &g_Af16[(size_t)(i0 + row_) * NN + k0_ + cb_ * 8]);               \
        }                                                                          \
        _Pragma("unroll") for (int rep = 0; rep < 2; rep++) {                      \
            int q_ = tid + rep * 256;                                              \
            int row_ = q_ >> 3, cb_ = q_ & 7;                                      \
            CP16(bb_ + IBH_OFF + row_ * 144 + cb_ * 16,                            \
                 &g_FtHi[(size_t)row_ * NN + k0_ + cb_ * 8]);                      \
        }                                                                          \
        CPCOMMIT();                                                                \
    } while (0)

            const int NT = (NN / KC) / 64;  // 16
            ITER_LOAD(0, 0);
            ITER_LOAD(1, 1);
            for (int t = 0; t < NT; t++) {
                if (t + 1 < NT) CPWAIT(1);
                else CPWAIT(0);
                __syncthreads();
                if (t + 2 < NT) ITER_LOAD(t + 2, (t + 2) % 3);
                const uint32_t bb = sb + (t % 3) * ITER_STAGE;
#pragma unroll
                for (int ks = 0; ks < 4; ks++) {
                    uint32_t ah[2][4], bh[2][4];
#pragma unroll
                    for (int mt = 0; mt < 2; mt++) {
                        uint32_t addr = bb + IA_OFF + (wm + mt * 16 + (lane & 15)) * 144 +
                                        ks * 32 + (lane >> 4) * 16;
                        LDSM4(ah[mt], addr);
                    }
#pragma unroll
                    for (int p = 0; p < 2; p++) {
                        uint32_t addr = bb + IBH_OFF +
                                        (wn + p * 16 + (lane & 7) + ((lane >> 4) & 1) * 8) * 144 +
                                        ks * 32 + ((lane >> 3) & 1) * 16;
                        LDSM4(bh[p], addr);
                    }
#pragma unroll
                    for (int mt = 0; mt < 2; mt++)
#pragma unroll
                        for (int p = 0; p < 2; p++) {
                            MMAF16(c[mt][p * 2 + 0], ah[mt], bh[p][0], bh[p][1]);
                            MMAF16(c[mt][p * 2 + 1], ah[mt], bh[p][2], bh[p][3]);
                        }
                }
            }

            const int gr = lane >> 2, gc = (lane & 3) * 2;
#pragma unroll
            for (int mt = 0; mt < 2; mt++)
#pragma unroll
                for (int nt = 0; nt < 4; nt++) {
                    float* base = &g_accp[((size_t)kc * NN + i0 + wm + mt * 16) * CC +
                                          wn + (nt >> 1) * 16 + (nt & 1) * 8];
                    *(float2*)&base[(size_t)gr * CC + gc] = make_float2(c[mt][nt][0], c[mt][nt][1]);
                    *(float2*)&base[(size_t)(gr + 8) * CC + gc] =
                        make_float2(c[mt][nt][2], c[mt][nt][3]);
                }
        } else {
            // ---- general SCAD path (smem overlay; L1-bypassing loads for mutable data) ----
            float* Yis = (float*)smem;
            float* YjWs = Yis + 64 * 32;
            float* Fjs = YjWs + 64 * 64;
            float* sqj = Fjs + 64 * 64;
            float* invdj = sqj + 64;
            float* qredf = invdj + 64;

            const int tx = tid & 15, ty = tid >> 4;
            const int jbase = kc * (NN / KC);

            const float lam = expf(log_lams[k]);
            const float thresh = 0.25f * lam * lam;
            const float inv_am1 = 1.0f / (SCAD_A_ - 1.0f);

            for (int sub = 0; sub < 4; sub++) {
                const int i0 = by * 128 + sub * 32;
                for (int l = tid; l < 512; l += 256) {
                    int kk = l >> 3, c4 = l & 7;
                    float4 v = ldcg4(&g_YT[kk * NN + i0 + c4 * 4]);
                    *(float4*)&Yis[kk * 32 + c4 * 4] = v;
                }
                const int iA = i0 + ty * 2;
                const float sqi0 = ldcgf(&g_sq[iA]), sqi1 = ldcgf(&g_sq[iA + 1]);
                const float di0 = g_invd[iA], di1 = g_invd[iA + 1];

                float acc[2][4] = {};
                float qacc[2] = {};

                for (int jt = 0; jt < (NN / KC) / 64; jt++) {
                    const int j0 = jbase + jt * 64;
                    for (int l = tid; l < 1024; l += 256) {
                        int row = l >> 4, c4 = l & 15;
                        *(float4*)&YjWs[row * 64 + c4 * 4] = ldcg4(&g_YT[row * NN + j0 + c4 * 4]);
                        *(float4*)&Fjs[row * 64 + c4 * 4] =
                            ldcg4(&F[(size_t)(j0 + row) * CC + c4 * 4]);
                    }
                    if (tid < 64) {
                        sqj[tid] = ldcgf(&g_sq[j0 + tid]);
                        invdj[tid] = g_invd[j0 + tid];
                    }
                    __syncthreads();

                    float s[2][4] = {};
#pragma unroll 16
                    for (int kk = 0; kk < 64; kk++) {
                        float2 a2 = *(const float2*)&Yis[kk * 32 + ty * 2];
                        float4 b = *(const float4*)&YjWs[kk * 64 + tx * 4];
                        s[0][0] = fmaf(a2.x, b.x, s[0][0]); s[0][1] = fmaf(a2.x, b.y, s[0][1]);
                        s[0][2] = fmaf(a2.x, b.z, s[0][2]); s[0][3] = fmaf(a2.x, b.w, s[0][3]);
                        s[1][0] = fmaf(a2.y, b.x, s[1][0]); s[1][1] = fmaf(a2.y, b.y, s[1][1]);
                        s[1][2] = fmaf(a2.y, b.z, s[1][2]); s[1][3] = fmaf(a2.y, b.w, s[1][3]);
                    }
                    __syncthreads();

#pragma unroll
                    for (int r = 0; r < 2; r++) {
                        const int gi = iA + r;
                        const float4 av = *(const float4*)&A[(size_t)gi * NN + j0 + tx * 4];
                        const float aarr[4] = {av.x, av.y, av.z, av.w};
                        const float sqi = r ? sqi1 : sqi0;
                        const float dii = r ? di1 : di0;
                        float qs = 0.0f;
#pragma unroll
                        for (int s2 = 0; s2 < 4; s2++) {
                            const int jl = tx * 4 + s2;
                            const int gj = j0 + jl;
                            float Z = fmaxf(sqi + sqj[jl] - 2.0f * s[r][s2], 0.0f);
                            float t = Z + DIST_EPS_;
                            float w;
                            if (t <= thresh) {
                                w = 1.0f;
                            } else {
                                float y = sqrtf(t);
                                float rho = (y <= lam) ? lam
                                                       : fmaxf(SCAD_A_ * lam - y, 0.0f) * inv_am1;
                                w = fminf(rho / (2.0f * y), 1.0f);
                            }
                            float aij = aarr[s2] + ((gi == gj) ? 1.0f : 0.0f);
                            float wt = w * aij * dii * invdj[jl];
                            YjWs[jl * 33 + ty * 2 + r] = wt;
                            qs += wt;
                        }
                        qacc[r] += qs;
                    }
                    __syncthreads();

#pragma unroll 16
                    for (int jj = 0; jj < 64; jj++) {
                        float a0 = YjWs[jj * 33 + ty * 2];
                        float a1 = YjWs[jj * 33 + ty * 2 + 1];
                        float4 b = *(const float4*)&Fjs[jj * 64 + tx * 4];
                        acc[0][0] = fmaf(a0, b.x, acc[0][0]); acc[0][1] = fmaf(a0, b.y, acc[0][1]);
                        acc[0][2] = fmaf(a0, b.z, acc[0][2]); acc[0][3] = fmaf(a0, b.w, acc[0][3]);
                        acc[1][0] = fmaf(a1, b.x, acc[1][0]); acc[1][1] = fmaf(a1, b.y, acc[1][1]);
                        acc[1][2] = fmaf(a1, b.z, acc[1][2]); acc[1][3] = fmaf(a1, b.w, acc[1][3]);
                    }
                    __syncthreads();
                }

#pragma unroll
                for (int r = 0; r < 2; r++) {
                    float4 st = make_float4(acc[r][0], acc[r][1], acc[r][2], acc[r][3]);
                    *(float4*)&g_accp[((size_t)kc * NN + iA + r) * CC + tx * 4] = st;
                    qredf[(ty * 2 + r) * 16 + tx] = qacc[r];
                }
                __syncthreads();
                if (tid < 32) {
                    float s = 0.0f;
#pragma unroll
                    for (int t2 = 0; t2 < 16; t2++) s += qredf[tid * 16 + t2];
                    g_qp[kc * NN + i0 + tid] = s;
                }
                __syncthreads();
            }
        }

        gridbar();

        // ---- combine + prep (blocks 0..63, 64 rows each) ----
        if (bid < 64) {
            float* s = (float*)smem;        // 64 x 65
            float* sq_s = s + 64 * 65;
            float* invd_s = sq_s + 64;
            const int j0 = bid * 64;
            if (tid < 64) invd_s[tid] = g_invd[j0 + tid];

            const int r = tid >> 2, cs = (tid & 3) * 16;
            const int row = j0 + r;
            const float lamv = g_lam[row];
            float denom;
            if (fastk) {
                denom = g_q0[row] + lamv;
            } else {
                float q = 0.0f;
#pragma unroll
                for (int c2 = 0; c2 < KC; c2++) q += ldcgf(&g_qp[c2 * NN + row]);
                denom = q + lamv;
            }
            const float invden = 1.0f / denom;
#pragma unroll
            for (int q = 0; q < 4; q++) {
                const size_t idx = (size_t)row * CC + cs + q * 4;
                float4 a = ldcg4(&g_accp[idx]);
#pragma unroll
                for (int c2 = 1; c2 < KC; c2++) {
                    float4 b = ldcg4(&g_accp[(size_t)c2 * NN * CC + idx]);
                    a.x += b.x; a.y += b.y; a.z += b.z; a.w += b.w;
                }
                float4 f0 = *(const float4*)&g_F0[idx];
                float4 v = make_float4((a.x + lamv * f0.x) * invden, (a.y + lamv * f0.y) * invden,
                                       (a.z + lamv * f0.z) * invden, (a.w + lamv * f0.w) * invden);
                *(float4*)&dst[idx] = v;
                s[r * 65 + cs + q * 4 + 0] = v.x;
                s[r * 65 + cs + q * 4 + 1] = v.y;
                s[r * 65 + cs + q * 4 + 2] = v.z;
                s[r * 65 + cs + q * 4 + 3] = v.w;
            }
            __syncthreads();
            if (k < K_ITER - 1) prep_from_smem(s, invd_s, sq_s, j0, k + 1, tid);
        }

        gridbar();
    }
}

// ---------------- launch ----------------
extern "C" void kernel_launch(void* const* d_in, const int* in_sizes, int n_in,
                              void* d_out, int out_size) {
    const float* A = (const float*)d_in[0];
    const float* X = (const float*)d_in[1];
    const float* W1 = (const float*)d_in[2];
    const float* b1 = (const float*)d_in[3];
    const float* W2 = (const float*)d_in[4];
    const float* b2 = (const float*)d_in[5];
    const float* log_lams = (const float*)d_in[6];
    const float* raw_alpha = (const float*)d_in[7];
    float* out = (float*)d_out;

    float* pF0;
    cudaGetSymbolAddress((void**)&pF0, g_F0);
    __half *pXhi, *pXlo, *pW1Thi, *pW1Tlo, *pW2Thi, *pW2Tlo, *pH1hi, *pH1lo;
    cudaGetSymbolAddress((void**)&pXhi, g_Xhi);
    cudaGetSymbolAddress((void**)&pXlo, g_Xlo);
    cudaGetSymbolAddress((void**)&pW1Thi, g_W1Thi);
    cudaGetSymbolAddress((void**)&pW1Tlo, g_W1Tlo);
    cudaGetSymbolAddress((void**)&pW2Thi, g_W2Thi);
    cudaGetSymbolAddress((void**)&pW2Tlo, g_W2Tlo);
    cudaGetSymbolAddress((void**)&pH1hi, g_H1hi);
    cudaGetSymbolAddress((void**)&pH1lo, g_H1lo);

    cudaFuncSetAttribute(persist_kernel, cudaFuncAttributeMaxDynamicSharedMemorySize, ITER_SMEM);
    cudaFuncSetAttribute(mlp_hmma<1, 1>, cudaFuncAttributeMaxDynamicSharedMemorySize, MLP_SMEM);
    cudaFuncSetAttribute(mlp_hmma<0, 2>, cudaFuncAttributeMaxDynamicSharedMemorySize, MLP_SMEM);

    deg_kernel<<<NN, 256>>>(A);
    asplit_kernel<<<NN, 256>>>(A);
    prepw_kernel<<<PW_XB + PW_W1B + PW_W2B, 256>>>(X, W1, W2);
    mlp_hmma<1, 1><<<dim3(HID / 64, NN / 128), 256, MLP_SMEM>>>(
        pXhi, pXlo, pW1Thi, pW1Tlo, b1, nullptr, nullptr, pH1hi, pH1lo, D_IN, HID);
    mlp_hmma<0, 2><<<dim3(1, NN / 128), 256, MLP_SMEM>>>(
        pH1hi, pH1lo, pW2Thi, pW2Tlo, b2, raw_alpha, pF0, nullptr, nullptr, HID, CC);
    persist_kernel<<<NBLK, 256, ITER_SMEM>>>(A, out, log_lams);
}

// round 15
// speedup vs baseline: 1.0965x; 1.0965x over previous
#include <cuda_runtime.h>
#include <cuda_fp16.h>
#include <math.h>
#include <stdint.h>

#define NN 4096
#define D_IN 512
#define HID 256
#define CC 64
#define K_ITER 10
#define KC 4   // split chunks (both paths)

#define SCAD_A_ 3.7f
#define LAM_BASE_ 0.11111111111111116f
#define EPS_ 1e-6f
#define DIST_EPS_ 1e-8f

// ---------------- static device scratch ----------------
__device__ __align__(16) __half g_Af16[(size_t)NN * NN];   // A_tilde fp16 [i][j]
__device__ __align__(16) __half g_FtHi[CC * NN];           // F^T fp16 [c][j]
__device__ __align__(16) __half g_Xhi[NN * D_IN];
__device__ __align__(16) __half g_Xlo[NN * D_IN];
__device__ __align__(16) __half g_W1Thi[HID * D_IN];
__device__ __align__(16) __half g_W1Tlo[HID * D_IN];
__device__ __align__(16) __half g_W2Thi[CC * HID];
__device__ __align__(16) __half g_W2Tlo[CC * HID];
__device__ __align__(16) __half g_H1hi[NN * HID];
__device__ __align__(16) __half g_H1lo[NN * HID];
__device__ __align__(16) float g_q0[NN];
__device__ __align__(16) float g_F0[NN * CC];
__device__ __align__(16) float g_Fa[NN * CC];
__device__ __align__(16) float g_Fb[NN * CC];
__device__ __align__(16) float g_YT[CC * NN];
__device__ __align__(16) float g_sq[NN];
__device__ __align__(16) float g_invd[NN];
__device__ __align__(16) float g_rawlam[NN];
__device__ __align__(16) float g_lam[NN];
__device__ __align__(16) float g_accp[(size_t)KC * NN * CC];
__device__ __align__(16) float g_qp[KC * NN];
__device__ int g_maxbits[K_ITER];  // atomicMax of float bits; replay-idempotent

__device__ __forceinline__ bool fast_ok(const float* __restrict__ log_lams, int k) {
    float lam = expf(log_lams[k]);
    float maxsq = __int_as_float(g_maxbits[k]);
    return 4.0f * maxsq + DIST_EPS_ <= 0.25f * lam * lam;
}

__device__ __forceinline__ uint32_t s2u(const void* p) {
    uint32_t a;
    asm("{ .reg .u64 t; cvta.to.shared.u64 t, %1; cvt.u32.u64 %0, t; }" : "=r"(a) : "l"(p));
    return a;
}
#define CP16(dst, src) asm volatile("cp.async.cg.shared.global [%0], [%1], 16;" :: "r"(dst), "l"(src))
#define CPCOMMIT() asm volatile("cp.async.commit_group;" ::: "memory")
#define CPWAIT(n) asm volatile("cp.async.wait_group %0;" :: "n"(n) : "memory")
#define LDSM4(r, addr)                                                             \
    asm volatile("ldmatrix.sync.aligned.m8n8.x4.shared.b16 {%0,%1,%2,%3}, [%4];"   \
                 : "=r"((r)[0]), "=r"((r)[1]), "=r"((r)[2]), "=r"((r)[3])          \
                 : "r"(addr))
#define MMAF16(c, a, b0, b1)                                                       \
    asm volatile("mma.sync.aligned.m16n8k16.row.col.f32.f16.f16.f32 "              \
                 "{%0,%1,%2,%3},{%4,%5,%6,%7},{%8,%9},{%0,%1,%2,%3};"              \
                 : "+f"((c)[0]), "+f"((c)[1]), "+f"((c)[2]), "+f"((c)[3])          \
                 : "r"((a)[0]), "r"((a)[1]), "r"((a)[2]), "r"((a)[3]),             \
                   "r"(b0), "r"(b1))

// ---------------- setup: degree ----------------
__global__ void deg_kernel(const float* __restrict__ A) {
    __shared__ float sm[256];
    int row = blockIdx.x;
    const float4* ap = (const float4*)(A + (size_t)row * NN);
    float s = 0.0f;
    for (int j = threadIdx.x; j < NN / 4; j += 256) {
        float4 v = ap[j];
        s += (v.x + v.y) + (v.z + v.w);
    }
    sm[threadIdx.x] = s;
    __syncthreads();
    for (int off = 128; off; off >>= 1) {
        if (threadIdx.x < off) sm[threadIdx.x] += sm[threadIdx.x + off];
        __syncthreads();
    }
    if (threadIdx.x == 0) g_invd[row] = 1.0f / sqrtf(sm[0] + 1.0f);
}

// ---------------- setup: A_tilde -> fp16 + q0 ----------------
__global__ void asplit_kernel(const float* __restrict__ A) {
    __shared__ float sm[256];
    const int i = blockIdx.x;
    const float di = g_invd[i];
    float qs = 0.0f;
    for (int j4 = threadIdx.x; j4 < NN / 4; j4 += 256) {
        const int j = j4 * 4;
        float4 a = *(const float4*)&A[(size_t)i * NN + j];
        float at[4];
        at[0] = (a.x + ((i == j + 0) ? 1.0f : 0.0f)) * di * g_invd[j + 0];
        at[1] = (a.y + ((i == j + 1) ? 1.0f : 0.0f)) * di * g_invd[j + 1];
        at[2] = (a.z + ((i == j + 2) ? 1.0f : 0.0f)) * di * g_invd[j + 2];
        at[3] = (a.w + ((i == j + 3) ? 1.0f : 0.0f)) * di * g_invd[j + 3];
        __align__(8) __half h[4];
#pragma unroll
        for (int t = 0; t < 4; t++) {
            qs += at[t];
            h[t] = __float2half_rn(at[t]);
        }
        *(uint2*)&g_Af16[(size_t)i * NN + j] = *(uint2*)&h[0];
    }
    sm[threadIdx.x] = qs;
    __syncthreads();
    for (int off = 128; off; off >>= 1) {
        if (threadIdx.x < off) sm[threadIdx.x] += sm[threadIdx.x + off];
        __syncthreads();
    }
    if (threadIdx.x == 0) g_q0[i] = sm[0];
}

// ---------------- setup: fused X split + W1/W2 transpose-split ----------------
#define PW_XB (NN * D_IN / 1024)          // 2048
#define PW_W1B ((D_IN / 32) * (HID / 32)) // 128
#define PW_W2B ((HID / 32) * (CC / 32))   // 16
__global__ void prepw_kernel(const float* __restrict__ X, const float* __restrict__ W1,
                             const float* __restrict__ W2) {
    __shared__ float t[32][33];
    const int b = blockIdx.x;
    const int tid = threadIdx.x;
    if (b < PW_XB) {
        int idx = b * 256 + tid;
        float4 v = *(const float4*)&X[(size_t)idx * 4];
        __align__(8) __half h[4], l[4];
        float a[4] = {v.x, v.y, v.z, v.w};
#pragma unroll
        for (int q = 0; q < 4; q++) {
            h[q] = __float2half_rn(a[q]);
            l[q] = __float2half_rn(a[q] - __half2float(h[q]));
        }
        *(uint2*)&g_Xhi[(size_t)idx * 4] = *(uint2*)&h[0];
        *(uint2*)&g_Xlo[(size_t)idx * 4] = *(uint2*)&l[0];
        return;
    }
    const float* S;
    __half *Dhi, *Dlo;
    int rows, cols, bi, bj;
    if (b < PW_XB + PW_W1B) {
        int bb = b - PW_XB;
        rows = D_IN; cols = HID;
        bi = (bb >> 3) * 32; bj = (bb & 7) * 32;
        S = W1; Dhi = g_W1Thi; Dlo = g_W1Tlo;
    } else {
        int bb = b - PW_XB - PW_W1B;
        rows = HID; cols = CC;
        bi = (bb >> 1) * 32; bj = (bb & 1) * 32;
        S = W2; Dhi = g_W2Thi; Dlo = g_W2Tlo;
    }
    const int tx = tid & 31, ty = tid >> 5;
#pragma unroll
    for (int r = 0; r < 4; r++)
        t[ty + r * 8][tx] = S[(size_t)(bi + ty + r * 8) * cols + bj + tx];
    __syncthreads();
#pragma unroll
    for (int r = 0; r < 4; r++) {
        float v = t[tx][ty + r * 8];
        __half h = __float2half_rn(v);
        __half l = __float2half_rn(v - __half2float(h));
        Dhi[(size_t)(bj + ty + r * 8) * rows + bi + tx] = h;
        Dlo[(size_t)(bj + ty + r * 8) * rows + bi + tx] = l;
    }
}

// ---------------- prep helper: from smem F-rows (stride 65) emit FtHi/YT/sq/max ----------------
__device__ __forceinline__ void prep_from_smem(const float* s, const float* invd_s,
                                               float* sq_s, int j0, int knext, int tid) {
    if (tid < 64) {
        float acc = 0.0f;
#pragma unroll 8
        for (int c = 0; c < 64; c++) { float x = s[tid * 65 + c]; acc = fmaf(x, x, acc); }
        float iv = invd_s[tid];
        float sqv = acc * iv * iv;
        g_sq[j0 + tid] = sqv;
        sq_s[tid] = sqv;
    }
    {
        const int c = tid >> 2;
        const int js = (tid & 3) * 16;
        __align__(16) __half hb[16];
        __align__(16) float yv[16];
#pragma unroll
        for (int t = 0; t < 16; t++) {
            float x = s[(js + t) * 65 + c];
            hb[t] = __float2half_rn(x);
            yv[t] = x * invd_s[js + t];
        }
        size_t ob = (size_t)c * NN + j0 + js;
        *(uint4*)&g_FtHi[ob] = *(uint4*)&hb[0];
        *(uint4*)&g_FtHi[ob + 8] = *(uint4*)&hb[8];
#pragma unroll
        for (int q = 0; q < 4; q++) *(float4*)&g_YT[ob + q * 4] = *(float4*)&yv[q * 4];
    }
    __syncthreads();
    if (tid == 0) {
        float m = sq_s[0];
#pragma unroll 8
        for (int t = 1; t < 64; t++) m = fmaxf(m, sq_s[t]);
        atomicMax(&g_maxbits[knext], __float_as_int(m));
    }
}

// ---------------- MLP HMMA (fp16, 3-pass, M=128, 2-stage). OUTMODE: 1 = half hi/lo, 2 = F0 + fused prep ----------------
#define AHI_OFF 0
#define ALO_OFF 10240
#define BHI_OFF 20480
#define BLO_OFF 25600
#define MLP_STAGE 30720
#define MLP_SMEM (2 * MLP_STAGE)
template <int RELU, int OUTMODE>
__global__ void __launch_bounds__(256) mlp_hmma(const __half* __restrict__ Ahi,
                                                const __half* __restrict__ Alo,
                                                const __half* __restrict__ Bhi,
                                                const __half* __restrict__ Blo,
                                                const float* __restrict__ bias,
                                                float* __restrict__ outF,
                                                __half* __restrict__ outHi,
                                                __half* __restrict__ outLo, int Kd, int Nd) {
    extern __shared__ char smem[];
    const uint32_t sb = s2u(smem);
    const int tid = threadIdx.x;
    const int wid = tid >> 5, lane = tid & 31;
    const int wm = (wid >> 1) * 32, wn = (wid & 1) * 32;
    const int i0 = blockIdx.y * 128, n0 = blockIdx.x * 64;

    float c[2][4][4];
#pragma unroll
    for (int a = 0; a < 2; a++)
#pragma unroll
        for (int b = 0; b < 4; b++)
#pragma unroll
            for (int d = 0; d < 4; d++) c[a][b][d] = 0.0f;

#define MLP_LOAD(T, BUF)                                                           \
    do {                                                                           \
        const int k0_ = (T) * 32;                                                  \
        const uint32_t bb_ = sb + (BUF) * MLP_STAGE;                               \
        _Pragma("unroll") for (int rep = 0; rep < 2; rep++) {                      \
            int q_ = tid + rep * 256;                                              \
            int row_ = q_ >> 2, cb_ = q_ & 3;                                      \
            CP16(bb_ + AHI_OFF + row_ * 80 + cb_ * 16,                             \
                 &Ahi[(size_t)(i0 + row_) * Kd + k0_ + cb_ * 8]);                  \
            CP16(bb_ + ALO_OFF + row_ * 80 + cb_ * 16,                             \
                 &Alo[(size_t)(i0 + row_) * Kd + k0_ + cb_ * 8]);                  \
        }                                                                          \
        {                                                                          \
            int row_ = tid >> 2, cb_ = tid & 3;                                    \
            CP16(bb_ + BHI_OFF + row_ * 80 + cb_ * 16,                             \
                 &Bhi[(size_t)(n0 + row_) * Kd + k0_ + cb_ * 8]);                  \
            CP16(bb_ + BLO_OFF + row_ * 80 + cb_ * 16,                             \
                 &Blo[(size_t)(n0 + row_) * Kd + k0_ + cb_ * 8]);                  \
        }                                                                          \
        CPCOMMIT();                                                                \
    } while (0)

    const int NT = Kd / 32;
    MLP_LOAD(0, 0);
    for (int t = 0; t < NT; t++) {
        if (t + 1 < NT) { MLP_LOAD(t + 1, (t + 1) & 1); CPWAIT(1); }
        else { CPWAIT(0); }
        __syncthreads();
        const uint32_t bb = sb + (t & 1) * MLP_STAGE;
#pragma unroll
        for (int ks = 0; ks < 2; ks++) {
            uint32_t ah[2][4], al[2][4], bh[2][4], bl[2][4];
#pragma unroll
            for (int mt = 0; mt < 2; mt++) {
                uint32_t addr = bb + AHI_OFF + (wm + mt * 16 + (lane & 15)) * 80 +
                                ks * 32 + (lane >> 4) * 16;
                LDSM4(ah[mt], addr);
                LDSM4(al[mt], addr + (ALO_OFF - AHI_OFF));
            }
#pragma unroll
            for (int p = 0; p < 2; p++) {
                uint32_t addr = bb + BHI_OFF +
                                (wn + p * 16 + (lane & 7) + ((lane >> 4) & 1) * 8) * 80 +
                                ks * 32 + ((lane >> 3) & 1) * 16;
                LDSM4(bh[p], addr);
                LDSM4(bl[p], addr + (BLO_OFF - BHI_OFF));
            }
#pragma unroll
            for (int mt = 0; mt < 2; mt++)
#pragma unroll
                for (int p = 0; p < 2; p++) {
                    MMAF16(c[mt][p * 2 + 0], ah[mt], bh[p][0], bh[p][1]);
                    MMAF16(c[mt][p * 2 + 1], ah[mt], bh[p][2], bh[p][3]);
                    MMAF16(c[mt][p * 2 + 0], ah[mt], bl[p][0], bl[p][1]);
                    MMAF16(c[mt][p * 2 + 1], ah[mt], bl[p][2], bl[p][3]);
                    MMAF16(c[mt][p * 2 + 0], al[mt], bh[p][0], bh[p][1]);
                    MMAF16(c[mt][p * 2 + 1], al[mt], bh[p][2], bh[p][3]);
                }
        }
        __syncthreads();
    }

    const int gr = lane >> 2, gc = (lane & 3) * 2;
    float* sbuf = (float*)smem;            // mode 2: 128 x 65
    float* invd_s = sbuf + 128 * 65;
    float* sq_s = invd_s + 128;
    if (OUTMODE == 2 && tid < 128) invd_s[tid] = g_invd[i0 + tid];
#pragma unroll
    for (int mt = 0; mt < 2; mt++)
#pragma unroll
        for (int nt = 0; nt < 4; nt++) {
            const int lcol = wn + (nt >> 1) * 16 + (nt & 1) * 8 + gc;
            const int col = n0 + lcol;
            const int lr0 = wm + mt * 16 + gr, lr1 = lr0 + 8;
            const int r0 = i0 + lr0, r1 = i0 + lr1;
            const float b0v = bias[col], b1v = bias[col + 1];
            float v00 = c[mt][nt][0] + b0v, v01 = c[mt][nt][1] + b1v;
            float v10 = c[mt][nt][2] + b0v, v11 = c[mt][nt][3] + b1v;
            if (RELU) {
                v00 = fmaxf(v00, 0.0f); v01 = fmaxf(v01, 0.0f);
                v10 = fmaxf(v10, 0.0f); v11 = fmaxf(v11, 0.0f);
            }
            if (OUTMODE == 1) {
                __half h00 = __float2half_rn(v00), h01 = __float2half_rn(v01);
                __half h10 = __float2half_rn(v10), h11 = __float2half_rn(v11);
                *(__half2*)&outHi[(size_t)r0 * Nd + col] = __halves2half2(h00, h01);
                *(__half2*)&outHi[(size_t)r1 * Nd + col] = __halves2half2(h10, h11);
                *(__half2*)&outLo[(size_t)r0 * Nd + col] = __halves2half2(
                    __float2half_rn(v00 - __half2float(h00)), __float2half_rn(v01 - __half2float(h01)));
                *(__half2*)&outLo[(size_t)r1 * Nd + col] = __halves2half2(
                    __float2half_rn(v10 - __half2float(h10)), __float2half_rn(v11 - __half2float(h11)));
            } else {
                *(float2*)&outF[(size_t)r0 * Nd + col] = make_float2(v00, v01);
                *(float2*)&outF[(size_t)r1 * Nd + col] = make_float2(v10, v11);
                if (OUTMODE == 2) {
                    sbuf[lr0 * 65 + lcol] = v00; sbuf[lr0 * 65 + lcol + 1] = v01;
                    sbuf[lr1 * 65 + lcol] = v10; sbuf[lr1 * 65 + lcol + 1] = v11;
                }
            }
        }
    if (OUTMODE == 2) {
        __syncthreads();
        prep_from_smem(sbuf, invd_s, sq_s, i0, 0, tid);
        prep_from_smem(sbuf + 64 * 65, invd_s + 64, sq_s + 64, i0 + 64, 0, tid);
    }
}

// ---------------- confidence / lambda ----------------
__global__ void conf_kernel(const float* __restrict__ F0, const float* __restrict__ raw_alpha) {
    int row = blockIdx.x * 8 + (threadIdx.x >> 5);
    int lane = threadIdx.x & 31;
    float v0 = F0[row * CC + lane], v1 = F0[row * CC + lane + 32];
    float m = fmaxf(v0, v1);
#pragma unroll
    for (int off = 16; off; off >>= 1) m = fmaxf(m, __shfl_xor_sync(0xffffffffu, m, off));
    float e = expf(v0 - m) + expf(v1 - m);
#pragma unroll
    for (int off = 16; off; off >>= 1) e += __shfl_xor_sync(0xffffffffu, e, off);
    if (lane == 0) {
        float conf = 1.0f / e;
        conf = fminf(fmaxf(conf, EPS_), 1.0f - EPS_);
        float alpha = log1pf(expf(raw_alpha[0])) + 0.5f;
        float base = fmaxf(1.0f - conf, EPS_);
        g_rawlam[row] = LAM_BASE_ * powf(base, alpha);
    }
}

__global__ void meanlam_kernel() {
    __shared__ float sm[1024];
    int tid = threadIdx.x;
    float s = 0.0f;
    for (int i = tid; i < NN; i += 1024) s += g_rawlam[i];
    sm[tid] = s;
    __syncthreads();
    for (int off = 512; off; off >>= 1) {
        if (tid < off) sm[tid] += sm[tid + off];
        __syncthreads();
    }
    float scale = LAM_BASE_ / fmaxf(sm[0] / (float)NN, EPS_);
    for (int i = tid; i < NN; i += 1024) g_lam[i] = fmaxf(g_rawlam[i] * scale, EPS_);
}

// ---------------- iteration kernel: fast fp16 HMMA path + general SCAD fallback ----------------
// grid (KC, NN/128)=128 blocks, 256 threads. Fast: BK=64, 4-stage ring, prefetch-3, single sync/stage.
#define IA_OFF 0
#define IBH_OFF 18432
#define ITER_STAGE 27648
#define ITER_SMEM (4 * ITER_STAGE)   // 110592 B; grid=128 <= 148 SMs so 1 CTA/SM regardless
__global__ void __launch_bounds__(256) iter_kernel(const float* __restrict__ A,
                                                   const float* __restrict__ F,
                                                   const float* __restrict__ log_lams, int k) {
    extern __shared__ char smem[];
    const int tid = threadIdx.x;
    const int kc = blockIdx.x;

    if (fast_ok(log_lams, k)) {
        const uint32_t sb = s2u(smem);
        const int wid = tid >> 5, lane = tid & 31;
        const int wm = (wid >> 1) * 32, wn = (wid & 1) * 32;
        const int i0 = blockIdx.y * 128;
        const int kbase = kc * (NN / KC);

        float c[2][4][4];
#pragma unroll
        for (int a = 0; a < 2; a++)
#pragma unroll
            for (int b = 0; b < 4; b++)
#pragma unroll
                for (int d = 0; d < 4; d++) c[a][b][d] = 0.0f;

#define ITER_LOAD(T, BUF)                                                          \
    do {                                                                           \
        const int k0_ = kbase + (T) * 64;                                          \
        const uint32_t bb_ = sb + (BUF) * ITER_STAGE;                              \
        _Pragma("unroll") for (int rep = 0; rep < 4; rep++) {                      \
            int q_ = tid + rep * 256;                                              \
            int row_ = q_ >> 3, cb_ = q_ & 7;                                      \
            CP16(bb_ + IA_OFF + row_ * 144 + cb_ * 16,                             \
                 &g_Af16[(size_t)(i0 + row_) * NN + k0_ + cb_ * 8]);               \
        }                                                                          \
        _Pragma("unroll") for (int rep = 0; rep < 2; rep++) {                      \
            int q_ = tid + rep * 256;                                              \
            int row_ = q_ >> 3, cb_ = q_ & 7;                                      \
            CP16(bb_ + IBH_OFF + row_ * 144 + cb_ * 16,                            \
                 &g_FtHi[(size_t)row_ * NN + k0_ + cb_ * 8]);                      \
        }                                                                          \
        CPCOMMIT();                                                                \
    } while (0)

        const int NT = (NN / KC) / 64;  // 16
        ITER_LOAD(0, 0);
        ITER_LOAD(1, 1);
        ITER_LOAD(2, 2);
        for (int t = 0; t < NT; t++) {
            // groups committed: min(t+3, NT); need group t done -> allow (committed - t - 1)
            if (t < NT - 3) CPWAIT(2);
            else if (t == NT - 3) CPWAIT(2);
            else if (t == NT - 2) CPWAIT(1);
            else CPWAIT(0);
            __syncthreads();  // single sync per stage; sync(t) proves compute(t-1) done
            if (t + 3 < NT) ITER_LOAD(t + 3, (t + 3) & 3);  // overwrites buffer (t-1)&3: safe
            const uint32_t bb = sb + (t & 3) * ITER_STAGE;
#pragma unroll
            for (int ks = 0; ks < 4; ks++) {
                uint32_t ah[2][4], bh[2][4];
#pragma unroll
                for (int mt = 0; mt < 2; mt++) {
                    uint32_t addr = bb + IA_OFF + (wm + mt * 16 + (lane & 15)) * 144 +
                                    ks * 32 + (lane >> 4) * 16;
                    LDSM4(ah[mt], addr);
                }
#pragma unroll
                for (int p = 0; p < 2; p++) {
                    uint32_t addr = bb + IBH_OFF +
                                    (wn + p * 16 + (lane & 7) + ((lane >> 4) & 1) * 8) * 144 +
                                    ks * 32 + ((lane >> 3) & 1) * 16;
                    LDSM4(bh[p], addr);
                }
#pragma unroll
                for (int mt = 0; mt < 2; mt++)
#pragma unroll
                    for (int p = 0; p < 2; p++) {
                        MMAF16(c[mt][p * 2 + 0], ah[mt], bh[p][0], bh[p][1]);
                        MMAF16(c[mt][p * 2 + 1], ah[mt], bh[p][2], bh[p][3]);
                    }
            }
        }

        const int gr = lane >> 2, gc = (lane & 3) * 2;
#pragma unroll
        for (int mt = 0; mt < 2; mt++)
#pragma unroll
            for (int nt = 0; nt < 4; nt++) {
                float* base = &g_accp[((size_t)kc * NN + i0 + wm + mt * 16) * CC +
                                      wn + (nt >> 1) * 16 + (nt & 1) * 8];
                *(float2*)&base[(size_t)gr * CC + gc] = make_float2(c[mt][nt][0], c[mt][nt][1]);
                *(float2*)&base[(size_t)(gr + 8) * CC + gc] = make_float2(c[mt][nt][2], c[mt][nt][3]);
            }
        return;
    }

    // ---------------- general SCAD path (overlay in dynamic smem) ----------------
    float* Yis = (float*)smem;       // [64][32]
    float* YjWs = Yis + 64 * 32;     // [64][64] Yj, then Ws stride 33
    float* Fjs = YjWs + 64 * 64;     // [64][64]
    float* sqj = Fjs + 64 * 64;      // [64]
    float* invdj = sqj + 64;         // [64]
    float* qredf = invdj + 64;       // [32][16]

    const int tx = tid & 15, ty = tid >> 4;
    const int jbase = kc * (NN / KC);  // 1024-wide j chunk

    const float lam = expf(log_lams[k]);
    const float thresh = 0.25f * lam * lam;
    const float inv_am1 = 1.0f / (SCAD_A_ - 1.0f);

    for (int sub = 0; sub < 4; sub++) {
        const int i0 = blockIdx.y * 128 + sub * 32;
        for (int l = tid; l < 512; l += 256) {
            int kk = l >> 3, c4 = l & 7;
            *(float4*)&Yis[kk * 32 + c4 * 4] = *(const float4*)&g_YT[kk * NN + i0 + c4 * 4];
        }
        const int iA = i0 + ty * 2;
        const float sqi0 = g_sq[iA], sqi1 = g_sq[iA + 1];
        const float di0 = g_invd[iA], di1 = g_invd[iA + 1];

        float acc[2][4] = {};
        float qacc[2] = {};

        for (int jt = 0; jt < (NN / KC) / 64; jt++) {  // 16 tiles
            const int j0 = jbase + jt * 64;
            for (int l = tid; l < 1024; l += 256) {
                int row = l >> 4, c4 = l & 15;
                *(float4*)&YjWs[row * 64 + c4 * 4] = *(const float4*)&g_YT[row * NN + j0 + c4 * 4];
                *(float4*)&Fjs[row * 64 + c4 * 4] = *(const float4*)&F[(size_t)(j0 + row) * CC + c4 * 4];
            }
            if (tid < 64) { sqj[tid] = g_sq[j0 + tid]; invdj[tid] = g_invd[j0 + tid]; }
            __syncthreads();

            float s[2][4] = {};
#pragma unroll 16
            for (int kk = 0; kk < 64; kk++) {
                float2 a2 = *(const float2*)&Yis[kk * 32 + ty * 2];
                float4 b = *(const float4*)&YjWs[kk * 64 + tx * 4];
                s[0][0] = fmaf(a2.x, b.x, s[0][0]); s[0][1] = fmaf(a2.x, b.y, s[0][1]);
                s[0][2] = fmaf(a2.x, b.z, s[0][2]); s[0][3] = fmaf(a2.x, b.w, s[0][3]);
                s[1][0] = fmaf(a2.y, b.x, s[1][0]); s[1][1] = fmaf(a2.y, b.y, s[1][1]);
                s[1][2] = fmaf(a2.y, b.z, s[1][2]); s[1][3] = fmaf(a2.y, b.w, s[1][3]);
            }
            __syncthreads();

#pragma unroll
            for (int r = 0; r < 2; r++) {
                const int gi = iA + r;
                const float4 av = *(const float4*)&A[(size_t)gi * NN + j0 + tx * 4];
                const float aarr[4] = {av.x, av.y, av.z, av.w};
                const float sqi = r ? sqi1 : sqi0;
                const float dii = r ? di1 : di0;
                float qs = 0.0f;
#pragma unroll
                for (int s2 = 0; s2 < 4; s2++) {
                    const int jl = tx * 4 + s2;
                    const int gj = j0 + jl;
                    float Z = fmaxf(sqi + sqj[jl] - 2.0f * s[r][s2], 0.0f);
                    float t = Z + DIST_EPS_;
                    float w;
                    if (t <= thresh) {
                        w = 1.0f;
                    } else {
                        float y = sqrtf(t);
                        float rho = (y <= lam) ? lam : fmaxf(SCAD_A_ * lam - y, 0.0f) * inv_am1;
                        w = fminf(rho / (2.0f * y), 1.0f);
                    }
                    float aij = aarr[s2] + ((gi == gj) ? 1.0f : 0.0f);
                    float wt = w * aij * dii * invdj[jl];
                    YjWs[jl * 33 + ty * 2 + r] = wt;
                    qs += wt;
                }
                qacc[r] += qs;
            }
            __syncthreads();

#pragma unroll 16
            for (int jj = 0; jj < 64; jj++) {
                float a0 = YjWs[jj * 33 + ty * 2];
                float a1 = YjWs[jj * 33 + ty * 2 + 1];
                float4 b = *(const float4*)&Fjs[jj * 64 + tx * 4];
                acc[0][0] = fmaf(a0, b.x, acc[0][0]); acc[0][1] = fmaf(a0, b.y, acc[0][1]);
                acc[0][2] = fmaf(a0, b.z, acc[0][2]); acc[0][3] = fmaf(a0, b.w, acc[0][3]);
                acc[1][0] = fmaf(a1, b.x, acc[1][0]); acc[1][1] = fmaf(a1, b.y, acc[1][1]);
                acc[1][2] = fmaf(a1, b.z, acc[1][2]); acc[1][3] = fmaf(a1, b.w, acc[1][3]);
            }
            __syncthreads();
        }

#pragma unroll
        for (int r = 0; r < 2; r++) {
            float4 st = make_float4(acc[r][0], acc[r][1], acc[r][2], acc[r][3]);
            *(float4*)&g_accp[((size_t)kc * NN + iA + r) * CC + tx * 4] = st;
            qredf[(ty * 2 + r) * 16 + tx] = qacc[r];
        }
        __syncthreads();
        if (tid < 32) {
            float s = 0.0f;
#pragma unroll
            for (int t2 = 0; t2 < 16; t2++) s += qredf[tid * 16 + t2];
            g_qp[kc * NN + i0 + tid] = s;
        }
        __syncthreads();
    }
}

// ---------------- combine + next-iteration prep (fused, separate kernel) ----------------
__global__ void __launch_bounds__(256) combine_prep_kernel(float* __restrict__ Fout,
                                                           const float* __restrict__ log_lams,
                                                           int k, int do_prep) {
    __shared__ float s[64 * 65];
    __shared__ float sq_s[64];
    __shared__ float invd_s[64];
    const int tid = threadIdx.x;
    const int j0 = blockIdx.x * 64;
    const bool fast = fast_ok(log_lams, k);
    if (tid < 64) invd_s[tid] = g_invd[j0 + tid];

    const int r = tid >> 2, cs = (tid & 3) * 16;
    const int row = j0 + r;
    const float lamv = g_lam[row];
    float denom;
    if (fast) {
        denom = g_q0[row] + lamv;
    } else {
        float q = 0.0f;
#pragma unroll
        for (int c2 = 0; c2 < KC; c2++) q += g_qp[c2 * NN + row];
        denom = q + lamv;
    }
    const float invden = 1.0f / denom;
#pragma unroll
    for (int q = 0; q < 4; q++) {
        const size_t idx = (size_t)row * CC + cs + q * 4;
        float4 a = *(const float4*)&g_accp[idx];
#pragma unroll
        for (int c2 = 1; c2 < KC; c2++) {
            float4 b = *(const float4*)&g_accp[(size_t)c2 * NN * CC + idx];
            a.x += b.x; a.y += b.y; a.z += b.z; a.w += b.w;
        }
        float4 f0 = *(const float4*)&g_F0[idx];
        float4 v = make_float4((a.x + lamv * f0.x) * invden, (a.y + lamv * f0.y) * invden,
                               (a.z + lamv * f0.z) * invden, (a.w + lamv * f0.w) * invden);
        *(float4*)&Fout[idx] = v;
        s[r * 65 + cs + q * 4 + 0] = v.x;
        s[r * 65 + cs + q * 4 + 1] = v.y;
        s[r * 65 + cs + q * 4 + 2] = v.z;
        s[r * 65 + cs + q * 4 + 3] = v.w;
    }
    __syncthreads();
    if (!do_prep) return;
    prep_from_smem(s, invd_s, sq_s, j0, k + 1, tid);
}

// ---------------- launch ----------------
extern "C" void kernel_launch(void* const* d_in, const int* in_sizes, int n_in,
                              void* d_out, int out_size) {
    const float* A = (const float*)d_in[0];
    const float* X = (const float*)d_in[1];
    const float* W1 = (const float*)d_in[2];
    const float* b1 = (const float*)d_in[3];
    const float* W2 = (const float*)d_in[4];
    const float* b2 = (const float*)d_in[5];
    const float* log_lams = (const float*)d_in[6];
    const float* raw_alpha = (const float*)d_in[7];
    float* out = (float*)d_out;

    float *pF0, *pFa, *pFb;
    cudaGetSymbolAddress((void**)&pF0, g_F0);
    cudaGetSymbolAddress((void**)&pFa, g_Fa);
    cudaGetSymbolAddress((void**)&pFb, g_Fb);
    __half *pXhi, *pXlo, *pW1Thi, *pW1Tlo, *pW2Thi, *pW2Tlo, *pH1hi, *pH1lo;
    cudaGetSymbolAddress((void**)&pXhi, g_Xhi);
    cudaGetSymbolAddress((void**)&pXlo, g_Xlo);
    cudaGetSymbolAddress((void**)&pW1Thi, g_W1Thi);
    cudaGetSymbolAddress((void**)&pW1Tlo, g_W1Tlo);
    cudaGetSymbolAddress((void**)&pW2Thi, g_W2Thi);
    cudaGetSymbolAddress((void**)&pW2Tlo, g_W2Tlo);
    cudaGetSymbolAddress((void**)&pH1hi, g_H1hi);
    cudaGetSymbolAddress((void**)&pH1lo, g_H1lo);

    cudaFuncSetAttribute(iter_kernel, cudaFuncAttributeMaxDynamicSharedMemorySize, ITER_SMEM);
    cudaFuncSetAttribute(mlp_hmma<1, 1>, cudaFuncAttributeMaxDynamicSharedMemorySize, MLP_SMEM);
    cudaFuncSetAttribute(mlp_hmma<0, 2>, cudaFuncAttributeMaxDynamicSharedMemorySize, MLP_SMEM);

    deg_kernel<<<NN, 256>>>(A);
    asplit_kernel<<<NN, 256>>>(A);
    prepw_kernel<<<PW_XB + PW_W1B + PW_W2B, 256>>>(X, W1, W2);
    mlp_hmma<1, 1><<<dim3(HID / 64, NN / 128), 256, MLP_SMEM>>>(
        pXhi, pXlo, pW1Thi, pW1Tlo, b1, nullptr, pH1hi, pH1lo, D_IN, HID);
    mlp_hmma<0, 2><<<dim3(1, NN / 128), 256, MLP_SMEM>>>(
        pH1hi, pH1lo, pW2Thi, pW2Tlo, b2, pF0, nullptr, nullptr, HID, CC);

    for (int k = 0; k < K_ITER; k++) {
        const float* src = (k == 0) ? pF0 : ((k & 1) ? pFa : pFb);
        float* dst = (k == K_ITER - 1) ? out : ((k & 1) ? pFb : pFa);
        iter_kernel<<<dim3(KC, NN / 128), 256, ITER_SMEM>>>(A, src, log_lams, k);
        if (k == 0) {
            conf_kernel<<<NN / 8, 256>>>(pF0, raw_alpha);
            meanlam_kernel<<<1, 1024>>>();
        }
        combine_prep_kernel<<<NN / 64, 256>>>(dst, log_lams, k, (k < K_ITER - 1) ? 1 : 0);
    }
}